// round 13
// baseline (speedup 1.0000x reference)
#include <cuda_runtime.h>

// ---------------------------------------------------------------------------
// TContextGGANN_39805756899562  —  R13: STG.256 probe (last untested axis)
//
// Algorithmic result (R1, re-verified through R12, rel_err = 0.0 exactly):
// the reference network has an exact fixed point at zero — hidden states
// start at zero, every message is elementwise-gated by a hidden state, the
// GRU maps (a=0,h=0)->0 bit-exactly, attention sees Q=K=V=0. Output is
// identically zero; kernel = 64 MiB zero-fill of poisoned d_out.
//
// Hardware result (R2-R12): bounded by the path-independent L2 write-
// acceptance ceiling ~2970 B/cyc (~5.86 TB/s @NAT); grid shape, block size,
// unroll, predication, TMA vs STG vs memset all flat at kernel 11.0-11.7 us,
// dur 12.77-13.06 us. R13 probes the one remaining untested lever:
// Blackwell 256-bit stores (st.global.v8.f32). If the ceiling is byte-rate
// limited (model) -> neutral; if sector-slot limited -> up to 2x. One run
// decides; fallback float4 kernel retained for generality.
// ---------------------------------------------------------------------------

__global__ void __launch_bounds__(256) tcg_zero8(float* __restrict__ out, int n8) {
    int t = blockIdx.x * blockDim.x + threadIdx.x;
    int total = gridDim.x * blockDim.x;
    // 2 x STG.256 per thread (64 bytes), coalesced, guarded.
    #pragma unroll
    for (int k = 0; k < 2; ++k) {
        int i = t + k * total;             // index in 32-byte units
        if (i < n8) {
            float* p = out + (size_t)i * 8;
            asm volatile(
                "st.global.v8.f32 [%0], {%1, %1, %1, %1, %1, %1, %1, %1};"
                :: "l"(p), "f"(0.0f) : "memory");
        }
    }
}

// Proven fallback (champion config) for any size not divisible by 8 floats.
__global__ void __launch_bounds__(256) tcg_zero4(float4* __restrict__ out, int n4) {
    int t = blockIdx.x * blockDim.x + threadIdx.x;
    int total = gridDim.x * blockDim.x;
    const float4 z = make_float4(0.0f, 0.0f, 0.0f, 0.0f);
    #pragma unroll
    for (int k = 0; k < 4; ++k) {
        int i = t + k * total;
        if (i < n4) out[i] = z;
    }
}

__global__ void tcg_zero_tail(float* __restrict__ out, int start, int n) {
    int i = start + blockIdx.x * blockDim.x + threadIdx.x;
    if (i < n) out[i] = 0.0f;
}

extern "C" void kernel_launch(void* const* d_in, const int* in_sizes, int n_in,
                              void* d_out, int out_size) {
    (void)d_in; (void)in_sizes; (void)n_in;

    float* out = (float*)d_out;
    int n = out_size;                 // 16,777,216 fp32 for this problem

    if ((n & 7) == 0) {
        // 256-bit store path: n8 32-byte chunks; d_out is 256B-aligned.
        int n8 = n >> 3;              // 2,097,152
        const int threads = 256;
        const int per_thread = 2;
        int blocks = (n8 + threads * per_thread - 1) / (threads * per_thread);
        tcg_zero8<<<blocks, threads>>>(out, n8);   // 4096 blocks here
    } else {
        int n4 = n >> 2;
        int rem_start = n4 << 2;
        if (n4 > 0) {
            const int threads = 256;
            const int per_thread = 4;
            int blocks = (n4 + threads * per_thread - 1) / (threads * per_thread);
            tcg_zero4<<<blocks, threads>>>((float4*)out, n4);
        }
        if (rem_start < n) {
            int rem = n - rem_start;
            int blocks = (rem + 127) / 128;
            tcg_zero_tail<<<blocks, 128>>>(out, rem_start, n);
        }
    }
}

// round 14
// speedup vs baseline: 1.0226x; 1.0226x over previous
#include <cuda_runtime.h>

// ---------------------------------------------------------------------------
// TContextGGANN_39805756899562  —  PERMANENT FINAL (sweep closed at R13)
//
// Algorithmic result (R1; re-verified 13x, rel_err = 0.0 exactly):
// the reference network has an exact fixed point at zero. All four hidden
// states initialize to zeros; every message is elementwise-gated by a hidden
// state (enc * h == 0); the GRU update (1-z)*h + z*tanh(a@Wox.T + (r*h)@Woh.T)
// maps (a=0, h=0) to exactly 0 (every term multiplies an exact 0.0 — no
// rounding enters); this holds across all LOOPS iterations; the final
// attention then sees Q=K=V=0, so A@V = 0. The returned (h_e, h_l, h_i, h_m)
// are identically zero for any inputs — the ~2e11 FLOPs of the apparent
// compute graph are dead code. The kernel reduces to a 64 MiB zero-fill of
// the 0xAA-poisoned d_out.
//
// Hardware result (R2-R13, exhaustive sweep): the zero-fill is bounded by
// the path-independent, byte-rate-limited L2 write-acceptance ceiling,
// ~2970 B/cyc (~5.86 TB/s @NAT) = 192 slices x ~16 B/cyc — half the 6300
// B/cyc load cap. ncu L2 ~50% = write half of the combined LTS port
// saturated. Full sweep:
//   STG.128 4096x256x4 (this) : kernel 11.04-11.52 us, dur 12.768-13.056
//   STG.128 2048x512x4        : 11.71 / 12.768
//   STG.128 8192x256x2        : 11.58 / 13.024
//   STG.128 1024x256x16       : 11.74 / 13.056
//   STG.128 exact-fit         : 11.39 / 13.056  (predicates free)
//   STG.256 4096x256x2        : 11.74 / 13.056  (byte-limited, not slot-)
//   TMA bulk stores           : 13.54 / 15.104
//   driver memset node        :   —   / 15.072
// Grid shape, block size, unroll, predication, store width, and write path
// are all flat at the floor; the dur-kernel gap (~1.6 us) is graph-replay
// overhead, node-type-independent (R5). 64 MiB / 5.86 TB/s = 11.2 us
// theoretical kernel floor; measured 11.0-11.5 us. This kernel is at the
// hardware roofline for its irreducible work.
// ---------------------------------------------------------------------------

__global__ void __launch_bounds__(256) tcg_zero4(float4* __restrict__ out, int n4) {
    int t = blockIdx.x * blockDim.x + threadIdx.x;
    int total = gridDim.x * blockDim.x;
    const float4 z = make_float4(0.0f, 0.0f, 0.0f, 0.0f);
    // 4 coalesced STG.128 per thread; fully unrolled, predicated bounds
    // (predicates measured free at issue ~11%).
    #pragma unroll
    for (int k = 0; k < 4; ++k) {
        int i = t + k * total;
        if (i < n4) out[i] = z;
    }
}

__global__ void tcg_zero_tail(float* __restrict__ out, int start, int n) {
    int i = start + blockIdx.x * blockDim.x + threadIdx.x;
    if (i < n) out[i] = 0.0f;
}

extern "C" void kernel_launch(void* const* d_in, const int* in_sizes, int n_in,
                              void* d_out, int out_size) {
    (void)d_in; (void)in_sizes; (void)n_in;

    float* out = (float*)d_out;
    int n  = out_size;            // 16,777,216 fp32 for this problem
    int n4 = n >> 2;              // float4 chunks; d_out is 256B-aligned
    int rem_start = n4 << 2;

    if (n4 > 0) {
        const int threads = 256;
        const int per_thread = 4;
        int blocks = (n4 + threads * per_thread - 1) / (threads * per_thread);
        tcg_zero4<<<blocks, threads>>>((float4*)out, n4);   // 4096 blocks here
    }
    if (rem_start < n) {          // never launched for n % 4 == 0
        int rem = n - rem_start;
        int blocks = (rem + 127) / 128;
        tcg_zero_tail<<<blocks, 128>>>(out, rem_start, n);
    }
}